// round 5
// baseline (speedup 1.0000x reference)
#include <cuda_runtime.h>
#include <cuda_bf16.h>
#include <cstdint>

// PCEN, 10 smoother coefficients.
//   m[s,t] = (1-s)*m[s,t-1] + s*x[t],  m[s,0] = x[0]
//   out = (x*(EPS+m)^(-alpha) + delta)^r - delta^r
//
// R5: MUFU-bound per R4 ncu (XU pipe ~76% at 4 MUFU/elem). Move the final
// exp2 to a polynomial on the FMA pipe (magic-constant int round, degree-5
// Taylor, SHF+IADD exponent insert) to rebalance XU 32->24 cyc/32elem vs
// FMA ~23. Scan: thread-serial float4 x warp Kogge-Stone, 2 chains/warp.

#define PCEN_EPS 1e-5f
#define NS 10
#define CPW 2
#define NPAIR (NS / CPW)
#define TT 2048
#define RPT 4
#define CHUNK (32 * RPT)
#define NCHUNK (TT / CHUNK)

__device__ __forceinline__ float fast_ex2(float v) {
    float r; asm("ex2.approx.ftz.f32 %0, %1;" : "=f"(r) : "f"(v)); return r;
}
__device__ __forceinline__ float fast_lg2(float v) {
    float r; asm("lg2.approx.ftz.f32 %0, %1;" : "=f"(r) : "f"(v)); return r;
}

// 2^v on FMA/ALU pipes (no MUFU). Valid for |v| < ~126.
__device__ __forceinline__ float poly_ex2(float v) {
    const float magic = 12582912.0f;           // 1.5 * 2^23
    float fl = v + magic;                      // RN -> integer in mantissa
    int   iv = __float_as_int(fl);             // low bits = round(v) (2's comp)
    float t  = v - (fl - magic);               // t in [-0.5, 0.5]
    float u  = t * 0.6931471805599453f;        // t*ln2
    float p  = fmaf(u, 8.3333333e-3f, 4.1666667e-2f);
    p = fmaf(p, u, 0.16666667f);
    p = fmaf(p, u, 0.5f);
    p = fmaf(p, u, 1.0f);
    p = fmaf(p, u, 1.0f);                      // e^u, rel err ~2.4e-6
    return __int_as_float(__float_as_int(p) + (iv << 23));
}

__global__ __launch_bounds__(128) void pcen_kernel(
    const float* __restrict__ x,
    const float* __restrict__ s_log,
    const float* __restrict__ alpha_log,
    const float* __restrict__ delta_log,
    const float* __restrict__ r_log,
    float* __restrict__ out,
    int F, int BF)
{
    const int gwarp = (blockIdx.x * blockDim.x + threadIdx.x) >> 5;
    const int lane  = threadIdx.x & 31;
    if (gwarp >= BF * NPAIR) return;

    const int row  = gwarp / NPAIR;
    const int pair = gwarp % NPAIR;
    const int i0   = pair * CPW;

    const int b = row / F;
    const int f = row % F;

    const float alpha = __expf(alpha_log[f]);
    const float delta = __expf(delta_log[f]);
    const float r     = __expf(r_log[f]);
    const float delta_r = fast_ex2(r * fast_lg2(delta));

    const float4* __restrict__ xp4 = (const float4*)(x + (size_t)row * TT);
    float* __restrict__ op = out + (((size_t)b * NS + i0) * F + f) * (size_t)TT;
    const size_t s_stride = (size_t)F * TT;

    float sv[CPW], a1[CPW], a2[CPW], a3[CPW], a4[CPW];
    float a8[CPW], a16[CPW], a32[CPW], a64[CPW];
    float a4lane[CPW], a128[CPW], carry[CPW];

    const float x0 = ((const float*)xp4)[0];

    #pragma unroll
    for (int c = 0; c < CPW; c++) {
        const float s = __expf(s_log[i0 + c]);
        sv[c] = s;
        const float a = 1.0f - s;
        a1[c]  = a;
        a2[c]  = a * a;
        a3[c]  = a2[c] * a;
        a4[c]  = a2[c] * a2[c];
        a8[c]  = a4[c] * a4[c];
        a16[c] = a8[c] * a8[c];
        a32[c] = a16[c] * a16[c];
        a64[c] = a32[c] * a32[c];
        a128[c] = a64[c] * a64[c];
        float ap = 1.0f;
        if (lane & 1)  ap *= a4[c];
        if (lane & 2)  ap *= a8[c];
        if (lane & 4)  ap *= a16[c];
        if (lane & 8)  ap *= a32[c];
        if (lane & 16) ap *= a64[c];
        a4lane[c] = ap;
        carry[c] = x0;   // m_{-1} = x0 -> m_0 = x0 (reference init)
    }

    for (int ch = 0; ch < NCHUNK; ch++) {
        const float4 xv = xp4[ch * 32 + lane];

        #pragma unroll
        for (int c = 0; c < CPW; c++) {
            const float s = sv[c];
            // local serial IIR (zero init)
            const float l0 = s * xv.x;
            const float l1 = fmaf(a1[c], l0, s * xv.y);
            const float l2 = fmaf(a1[c], l1, s * xv.z);
            const float l3 = fmaf(a1[c], l2, s * xv.w);

            // Kogge-Stone over lane aggregates (ratio a^4)
            float S = l3;
            float v;
            v = __shfl_up_sync(0xFFFFFFFFu, S, 1);  if (lane >= 1)  S = fmaf(a4[c],  v, S);
            v = __shfl_up_sync(0xFFFFFFFFu, S, 2);  if (lane >= 2)  S = fmaf(a8[c],  v, S);
            v = __shfl_up_sync(0xFFFFFFFFu, S, 4);  if (lane >= 4)  S = fmaf(a16[c], v, S);
            v = __shfl_up_sync(0xFFFFFFFFu, S, 8);  if (lane >= 8)  S = fmaf(a32[c], v, S);
            v = __shfl_up_sync(0xFFFFFFFFu, S, 16); if (lane >= 16) S = fmaf(a64[c], v, S);

            const float P = __shfl_up_sync(0xFFFFFFFFu, S, 1);
            const float Mprev = (lane == 0) ? carry[c]
                                            : fmaf(a4lane[c], carry[c], P);
            const float S31 = __shfl_sync(0xFFFFFFFFu, S, 31);
            carry[c] = fmaf(a128[c], carry[c], S31);

            const float m0 = fmaf(a1[c], Mprev, l0);
            const float m1 = fmaf(a2[c], Mprev, l1);
            const float m2 = fmaf(a3[c], Mprev, l2);
            const float m3 = fmaf(a4[c], Mprev, l3);

            float4 o;
            {
                const float sm = fast_ex2(-alpha * fast_lg2(PCEN_EPS + m0));
                o.x = poly_ex2(r * fast_lg2(fmaf(xv.x, sm, delta))) - delta_r;
            }
            {
                const float sm = fast_ex2(-alpha * fast_lg2(PCEN_EPS + m1));
                o.y = poly_ex2(r * fast_lg2(fmaf(xv.y, sm, delta))) - delta_r;
            }
            {
                const float sm = fast_ex2(-alpha * fast_lg2(PCEN_EPS + m2));
                o.z = poly_ex2(r * fast_lg2(fmaf(xv.z, sm, delta))) - delta_r;
            }
            {
                const float sm = fast_ex2(-alpha * fast_lg2(PCEN_EPS + m3));
                o.w = poly_ex2(r * fast_lg2(fmaf(xv.w, sm, delta))) - delta_r;
            }
            *(float4*)(op + (size_t)c * s_stride + (size_t)ch * CHUNK + lane * RPT) = o;
        }
    }
}

extern "C" void kernel_launch(void* const* d_in, const int* in_sizes, int n_in,
                              void* d_out, int out_size)
{
    const float* x         = (const float*)d_in[0];
    const float* s_log     = (const float*)d_in[1];
    const float* alpha_log = (const float*)d_in[2];
    const float* delta_log = (const float*)d_in[3];
    const float* r_log     = (const float*)d_in[4];
    float* out = (float*)d_out;

    const int F  = in_sizes[2];
    const int BF = in_sizes[0] / TT;

    const int total_warps = BF * NPAIR;
    const int threads = 128;
    const int warps_per_block = threads / 32;
    const int blocks = (total_warps + warps_per_block - 1) / warps_per_block;

    pcen_kernel<<<blocks, threads>>>(x, s_log, alpha_log, delta_log, r_log,
                                     out, F, BF);
}